// round 3
// baseline (speedup 1.0000x reference)
#include <cuda_runtime.h>

#define S 8
#define N 512
#define C 128
#define H 128
#define W 128
#define LEVELS 4
#define KK 49
#define OUT_F 972
#define PLANE_ELEMS 22282240   // (8*(128*128+64*64+32*32+16*16)) * 128

// Scratch: channel-last fmap pyramids + target features (static device globals, no allocs)
__device__ float g_pyr[3][PLANE_ELEMS];
__device__ float g_tfeat[3][N][C];

// Level offsets in "position" units (positions * C = float offset)
// L0: 0            (S*16384)
// L1: 131072       (S*4096)
// L2: 163840       (S*1024)
// L3: 172032       (S*256)

// ---------------------------------------------------------------------------
// 1) Transpose [S,C,H,W] -> [S,H,W,C] (channel-last level 0)
// ---------------------------------------------------------------------------
__global__ void transpose_kernel(const float* __restrict__ in0,
                                 const float* __restrict__ in1,
                                 const float* __restrict__ in2) {
    int plane = blockIdx.z;
    const float* __restrict__ in = (plane == 0) ? in0 : (plane == 1) ? in1 : in2;
    float* __restrict__ out = g_pyr[plane];

    int sh = blockIdx.x;            // s*H + h
    int tileid = blockIdx.y;        // 16 tiles of 32x32 over (c, w)
    int c0 = (tileid >> 2) * 32;
    int w0 = (tileid & 3) * 32;

    __shared__ float tile[32][33];
    int tx = threadIdx.x, ty = threadIdx.y;   // (32, 8)

    int s = sh >> 7;                 // /H
    int h = sh & 127;
    const float* __restrict__ inp = in + (size_t)s * C * H * W + (size_t)h * W;
#pragma unroll
    for (int i = 0; i < 32; i += 8)
        tile[ty + i][tx] = inp[(size_t)(c0 + ty + i) * (H * W) + (w0 + tx)];
    __syncthreads();
    float* __restrict__ outp = out + (size_t)sh * W * C;
#pragma unroll
    for (int i = 0; i < 32; i += 8)
        outp[(size_t)(w0 + ty + i) * C + (c0 + tx)] = tile[tx][ty + i];
}

// ---------------------------------------------------------------------------
// 2) Avg-pool 2x2 in channel-last layout (level l -> l+1), float4 per thread
// ---------------------------------------------------------------------------
__global__ void pool_kernel(long src_loff, long dst_loff, int Wsrc) {
    int plane = blockIdx.z;
    int Wd = Wsrc >> 1;
    int idx = blockIdx.x;            // s*Wd*Wd + h*Wd + w
    int c4 = threadIdx.x;            // 0..31, handles channels c4*4 .. c4*4+3
    int w = idx % Wd; idx /= Wd;
    int h = idx % Wd;
    int sfr = idx / Wd;

    float* __restrict__ base = g_pyr[plane];
    long p00 = src_loff + ((long)sfr * Wsrc + 2 * h) * Wsrc + 2 * w;
    const float4* a = (const float4*)(base + p00 * C) + c4;
    const float4* b = (const float4*)(base + (p00 + 1) * C) + c4;
    const float4* cp = (const float4*)(base + (p00 + Wsrc) * C) + c4;
    const float4* d = (const float4*)(base + (p00 + Wsrc + 1) * C) + c4;
    float4 va = *a, vb = *b, vc = *cp, vd = *d;
    float4 r;
    r.x = 0.25f * (va.x + vb.x + vc.x + vd.x);
    r.y = 0.25f * (va.y + vb.y + vc.y + vd.y);
    r.z = 0.25f * (va.z + vb.z + vc.z + vd.z);
    r.w = 0.25f * (va.w + vb.w + vc.w + vd.w);
    long pd = dst_loff + ((long)sfr * Wd + h) * Wd + w;
    ((float4*)(base + pd * C))[c4] = r;
}

// ---------------------------------------------------------------------------
// 3) Target features: bilinear at frame queried_t[n], coords of frame 0
// ---------------------------------------------------------------------------
__global__ void tfeat_kernel(const float* __restrict__ coords,
                             const int* __restrict__ qt) {
    int plane = blockIdx.y;
    int n = blockIdx.x;
    int c = threadIdx.x;
    int t = qt[n];
    float x = coords[n * 3 + 0];
    float y = coords[n * 3 + 1];
    float z = coords[n * 3 + 2];
    float cx, cy;
    if (plane == 0)      { cx = x; cy = y; }
    else if (plane == 1) { cx = y; cy = z; }
    else                 { cx = x; cy = z; }

    cx = fminf(fmaxf(cx, 0.f), (float)(W - 1));
    cy = fminf(fmaxf(cy, 0.f), (float)(H - 1));
    int x0 = min((int)floorf(cx), W - 2);
    int y0 = min((int)floorf(cy), H - 2);
    float wx = cx - (float)x0, wy = cy - (float)y0;

    const float* __restrict__ b = g_pyr[plane] + (((long)t * H + y0) * W + x0) * C + c;
    float v00 = b[0], v01 = b[C];
    float v10 = b[(long)W * C], v11 = b[(long)W * C + C];
    g_tfeat[plane][n][c] = v00 * (1.f - wx) * (1.f - wy) + v01 * wx * (1.f - wy)
                         + v10 * (1.f - wx) * wy + v11 * wx * wy;
}

// ---------------------------------------------------------------------------
// 4) Main: per (plane, s, n): pyramid patch dots + window bilinear + feats
// ---------------------------------------------------------------------------
__global__ __launch_bounds__(128) void main_kernel(const float* __restrict__ coords,
                                                   float* __restrict__ out) {
    const long LOFF[4] = {0L, 131072L, 163840L, 172032L};
    const float INV_SQRT_C = 0.08838834764831845f;   // 1/sqrt(128)

    int plane = blockIdx.y;
    int sn = blockIdx.x;                  // s*N + n
    int n = sn & (N - 1);
    int sfr = sn >> 9;                    // /N
    int tid = threadIdx.x;
    int warp = tid >> 5, lane = tid & 31;

    __shared__ float t_sh[C];
    __shared__ float patch[64];

    float cx, cy;
    {
        const float* __restrict__ cp = coords + (long)sn * 3;
        float x = cp[0], y = cp[1], z = cp[2];
        if (plane == 0)      { cx = x; cy = y; }
        else if (plane == 1) { cx = y; cy = z; }
        else                 { cx = x; cy = z; }
    }

    t_sh[tid] = g_tfeat[plane][n][tid];
    __syncthreads();
    float4 t4 = *(const float4*)&t_sh[lane * 4];

    const float* __restrict__ pbase = g_pyr[plane];
    float* __restrict__ outcorr = out + (long)sn * OUT_F + plane * (LEVELS * KK);

#pragma unroll
    for (int l = 0; l < LEVELS; ++l) {
        int Wl = W >> l;
        float inv = 1.0f / (float)(1 << l);
        float cxl = cx * inv, cyl = cy * inv;

        int x0a[7]; float wxa[7];
        int y0a[7]; float wya[7];
#pragma unroll
        for (int j = 0; j < 7; ++j) {
            float xs = fminf(fmaxf(cxl + (float)(j - 3), 0.f), (float)(Wl - 1));
            int x0 = min((int)floorf(xs), Wl - 2);
            x0a[j] = x0; wxa[j] = xs - (float)x0;
            float ys = fminf(fmaxf(cyl + (float)(j - 3), 0.f), (float)(Wl - 1));
            int y0 = min((int)floorf(ys), Wl - 2);
            y0a[j] = y0; wya[j] = ys - (float)y0;
        }
        int xb = x0a[0], yb = y0a[0];

        long fr = LOFF[l] + (long)sfr * Wl * Wl;
        // 64 patch dots: warp w handles positions w*16 .. w*16+15
#pragma unroll 4
        for (int i = 0; i < 16; ++i) {
            int p = warp * 16 + i;
            int iy = p >> 3, ix = p & 7;
            int xx = min(xb + ix, Wl - 1);
            int yy = min(yb + iy, Wl - 1);
            const float4 f = *(const float4*)(pbase + (fr + (long)yy * Wl + xx) * C + lane * 4);
            float d = f.x * t4.x + f.y * t4.y + f.z * t4.z + f.w * t4.w;
            d += __shfl_xor_sync(0xffffffffu, d, 16);
            d += __shfl_xor_sync(0xffffffffu, d, 8);
            d += __shfl_xor_sync(0xffffffffu, d, 4);
            d += __shfl_xor_sync(0xffffffffu, d, 2);
            d += __shfl_xor_sync(0xffffffffu, d, 1);
            if (lane == 0) patch[p] = d * INV_SQRT_C;
        }
        __syncthreads();

        if (tid < KK) {
            int kx = tid % 7, ky = tid / 7;
            int ix = x0a[kx] - xb;
            int iy = y0a[ky] - yb;
            float wx = wxa[kx], wy = wya[ky];
            float v = patch[iy * 8 + ix]           * (1.f - wx) * (1.f - wy)
                    + patch[iy * 8 + ix + 1]       * wx         * (1.f - wy)
                    + patch[(iy + 1) * 8 + ix]     * (1.f - wx) * wy
                    + patch[(iy + 1) * 8 + ix + 1] * wx         * wy;
            outcorr[l * KK + tid] = v;
        }
        __syncthreads();
    }

    // current triplane feature: bilinear at level 0, frame s
    {
        float xs = fminf(fmaxf(cx, 0.f), (float)(W - 1));
        float ys = fminf(fmaxf(cy, 0.f), (float)(H - 1));
        int x0 = min((int)floorf(xs), W - 2);
        int y0 = min((int)floorf(ys), H - 2);
        float wx = xs - (float)x0, wy = ys - (float)y0;
        const float* __restrict__ b = pbase + (((long)sfr * H + y0) * W + x0) * C + tid;
        float v00 = b[0], v01 = b[C];
        float v10 = b[(long)W * C], v11 = b[(long)W * C + C];
        float v = v00 * (1.f - wx) * (1.f - wy) + v01 * wx * (1.f - wy)
                + v10 * (1.f - wx) * wy + v11 * wx * wy;
        out[(long)sn * OUT_F + 3 * LEVELS * KK + plane * C + tid] = v;
    }
}

// ---------------------------------------------------------------------------
extern "C" void kernel_launch(void* const* d_in, const int* in_sizes, int n_in,
                              void* d_out, int out_size) {
    const float* fxy    = (const float*)d_in[0];
    const float* fyz    = (const float*)d_in[1];
    const float* fxz    = (const float*)d_in[2];
    const float* coords = (const float*)d_in[3];
    const int*   qt     = (const int*)d_in[4];
    float* out = (float*)d_out;
    (void)in_sizes; (void)n_in; (void)out_size;

    // 1) transpose to channel-last level 0
    {
        dim3 grid(S * H, 16, 3), block(32, 8);
        transpose_kernel<<<grid, block>>>(fxy, fyz, fxz);
    }
    // 2) pyramid pools (float4 per thread, 32 threads)
    {
        dim3 g1(S * 64 * 64, 1, 3);
        pool_kernel<<<g1, 32>>>(0L,      131072L, 128);
        dim3 g2(S * 32 * 32, 1, 3);
        pool_kernel<<<g2, 32>>>(131072L, 163840L, 64);
        dim3 g3(S * 16 * 16, 1, 3);
        pool_kernel<<<g3, 32>>>(163840L, 172032L, 32);
    }
    // 3) target features
    {
        dim3 grid(N, 3);
        tfeat_kernel<<<grid, 128>>>(coords, qt);
    }
    // 4) main lookup
    {
        dim3 grid(S * N, 3);
        main_kernel<<<grid, 128>>>(coords, out);
    }
}

// round 5
// speedup vs baseline: 1.1758x; 1.1758x over previous
#include <cuda_runtime.h>

#define S 8
#define N 512
#define C 128
#define H 128
#define W 128
#define LEVELS 4
#define KK 49
#define OUT_F 972
#define PLANE_ELEMS 22282240   // (8*(128*128+64*64+32*32+16*16)) * 128

// Scratch: channel-last fmap pyramid per plane (static device global, no allocs)
__device__ float g_pyr[3][PLANE_ELEMS];

// Level offsets in "position" units (positions * C = float offset)
// L0: 0        (S*16384)
// L1: 131072   (S*4096)
// L2: 163840   (S*1024)
// L3: 172032   (S*256)

// ---------------------------------------------------------------------------
// 1) Fused transpose + L1 pool: [S,C,H,W] -> [S,H,W,C] level 0, and emit L1.
//    Block covers (s, h-pair) x (32c x 32w tile). grid (S*64, 16, 3)
// ---------------------------------------------------------------------------
__global__ void transpose_pool_kernel(const float* __restrict__ in0,
                                      const float* __restrict__ in1,
                                      const float* __restrict__ in2) {
    int plane = blockIdx.z;
    const float* __restrict__ in = (plane == 0) ? in0 : (plane == 1) ? in1 : in2;
    float* __restrict__ out = g_pyr[plane];

    int shp = blockIdx.x;            // s*64 + hp
    int s = shp >> 6;
    int hp = shp & 63;               // h-pair: rows 2hp, 2hp+1
    int tileid = blockIdx.y;
    int c0 = (tileid >> 2) * 32;
    int w0 = (tileid & 3) * 32;

    __shared__ float t0[32][33];     // [c_off][w_off] for row 2hp
    __shared__ float t1[32][33];     // row 2hp+1
    int tx = threadIdx.x, ty = threadIdx.y;   // (32, 8)

    const float* __restrict__ inp = in + (size_t)s * C * H * W + (size_t)(2 * hp) * W;
#pragma unroll
    for (int i = 0; i < 32; i += 8) {
        t0[ty + i][tx] = inp[(size_t)(c0 + ty + i) * (H * W) + (w0 + tx)];
        t1[ty + i][tx] = inp[(size_t)(c0 + ty + i) * (H * W) + W + (w0 + tx)];
    }
    __syncthreads();

    // L0 writes (channel-last)
    float* __restrict__ o0 = out + (size_t)(s * H + 2 * hp) * W * C;
    float* __restrict__ o1 = o0 + (size_t)W * C;
#pragma unroll
    for (int i = 0; i < 32; i += 8) {
        o0[(size_t)(w0 + ty + i) * C + (c0 + tx)] = t0[tx][ty + i];
        o1[(size_t)(w0 + ty + i) * C + (c0 + tx)] = t1[tx][ty + i];
    }

    // L1 writes: pool 2x2 -> 16 L1 columns of this w-tile, row hp
    const long L1o = 131072L;
#pragma unroll
    for (int k = 0; k < 2; ++k) {
        int wp = ty + k * 8;                    // 0..15
        float v = t0[tx][2 * wp] + t0[tx][2 * wp + 1]
                + t1[tx][2 * wp] + t1[tx][2 * wp + 1];
        long pos = L1o + (((long)s * 64 + hp) * 64 + (w0 >> 1) + wp);
        out[pos * C + (c0 + tx)] = 0.25f * v;
    }
}

// ---------------------------------------------------------------------------
// 2) Fused L1->L2->L3 pool. Block covers (s, L3-row r): L2 rows 2r,2r+1 + L3 row r
//    grid (S*16, 1, 3), 256 threads
// ---------------------------------------------------------------------------
__global__ __launch_bounds__(256) void pool23_kernel() {
    int plane = blockIdx.z;
    int idx = blockIdx.x;              // s*16 + r
    int sfr = idx >> 4;
    int r = idx & 15;
    float* __restrict__ base = g_pyr[plane];
    const long L1o = 131072L, L2o = 163840L, L3o = 172032L;

    __shared__ float4 s2[2][32][32];   // [l2row_local][col][c4]
    int tid = threadIdx.x;
    int warp = tid >> 5, lane = tid & 31;

    // L2: 64 positions (2 rows x 32 cols); warp handles 8
#pragma unroll
    for (int i = 0; i < 8; ++i) {
        int p = warp * 8 + i;
        int row2 = p >> 5, col2 = p & 31;
        int gr2 = r * 2 + row2;
        long l1p = L1o + (((long)sfr * 64 + gr2 * 2) * 64 + col2 * 2);
        float4 a = ((const float4*)(base + l1p * C))[lane];
        float4 b = ((const float4*)(base + (l1p + 1) * C))[lane];
        float4 c = ((const float4*)(base + (l1p + 64) * C))[lane];
        float4 d = ((const float4*)(base + (l1p + 65) * C))[lane];
        float4 v;
        v.x = 0.25f * (a.x + b.x + c.x + d.x);
        v.y = 0.25f * (a.y + b.y + c.y + d.y);
        v.z = 0.25f * (a.z + b.z + c.z + d.z);
        v.w = 0.25f * (a.w + b.w + c.w + d.w);
        long l2p = L2o + (((long)sfr * 32 + gr2) * 32 + col2);
        ((float4*)(base + l2p * C))[lane] = v;
        s2[row2][col2][lane] = v;
    }
    __syncthreads();

    // L3: 16 positions in row r; warp handles 2
#pragma unroll
    for (int i = 0; i < 2; ++i) {
        int p = warp * 2 + i;          // col3 0..15
        float4 a = s2[0][2 * p][lane],     b = s2[0][2 * p + 1][lane];
        float4 c = s2[1][2 * p][lane],     d = s2[1][2 * p + 1][lane];
        float4 v;
        v.x = 0.25f * (a.x + b.x + c.x + d.x);
        v.y = 0.25f * (a.y + b.y + c.y + d.y);
        v.z = 0.25f * (a.z + b.z + c.z + d.z);
        v.w = 0.25f * (a.w + b.w + c.w + d.w);
        long l3p = L3o + (((long)sfr * 16 + r) * 16 + p);
        ((float4*)(base + l3p * C))[lane] = v;
    }
}

// ---------------------------------------------------------------------------
// 3) Main: per (plane, s, n): inline tfeat + pyramid patch dots + window
//    bilinear + current feature. grid (S*N, 3), 128 threads
// ---------------------------------------------------------------------------
__global__ __launch_bounds__(128) void main_kernel(const float* __restrict__ coords,
                                                   const int* __restrict__ qt,
                                                   float* __restrict__ out) {
    const long LOFF[4] = {0L, 131072L, 163840L, 172032L};
    const float INV_SQRT_C = 0.08838834764831845f;   // 1/sqrt(128)

    int plane = blockIdx.y;
    int sn = blockIdx.x;                  // s*N + n
    int n = sn & (N - 1);
    int sfr = sn >> 9;
    int tid = threadIdx.x;
    int warp = tid >> 5, lane = tid & 31;

    __shared__ float t_sh[C];
    __shared__ float patch[64];

    const float* __restrict__ pbase = g_pyr[plane];

    float cx, cy;
    {
        const float* __restrict__ cp = coords + (long)sn * 3;
        float x = cp[0], y = cp[1], z = cp[2];
        if (plane == 0)      { cx = x; cy = y; }
        else if (plane == 1) { cx = y; cy = z; }
        else                 { cx = x; cy = z; }
    }

    // --- inline tfeat: bilinear at frame qt[n] with frame-0 coords ---
    {
        const float* __restrict__ cp0 = coords + (long)n * 3;   // s = 0
        float x = cp0[0], y = cp0[1], z = cp0[2];
        float fx, fy;
        if (plane == 0)      { fx = x; fy = y; }
        else if (plane == 1) { fx = y; fy = z; }
        else                 { fx = x; fy = z; }
        fx = fminf(fmaxf(fx, 0.f), (float)(W - 1));
        fy = fminf(fmaxf(fy, 0.f), (float)(H - 1));
        int qx0 = min((int)floorf(fx), W - 2);
        int qy0 = min((int)floorf(fy), H - 2);
        float wx = fx - (float)qx0, wy = fy - (float)qy0;
        int t = qt[n];
        const float* __restrict__ b = pbase + (((long)t * H + qy0) * W + qx0) * C + tid;
        float v00 = b[0], v01 = b[C];
        float v10 = b[(long)W * C], v11 = b[(long)W * C + C];
        t_sh[tid] = v00 * (1.f - wx) * (1.f - wy) + v01 * wx * (1.f - wy)
                  + v10 * (1.f - wx) * wy + v11 * wx * wy;
    }
    __syncthreads();
    float4 t4 = *(const float4*)&t_sh[lane * 4];

    float* __restrict__ outcorr = out + (long)sn * OUT_F + plane * (LEVELS * KK);

#pragma unroll
    for (int l = 0; l < LEVELS; ++l) {
        int Wl = W >> l;
        float inv = 1.0f / (float)(1 << l);
        float cxl = cx * inv, cyl = cy * inv;

        int x0a[7]; float wxa[7];
        int y0a[7]; float wya[7];
#pragma unroll
        for (int j = 0; j < 7; ++j) {
            float xs = fminf(fmaxf(cxl + (float)(j - 3), 0.f), (float)(Wl - 1));
            int x0 = min((int)floorf(xs), Wl - 2);
            x0a[j] = x0; wxa[j] = xs - (float)x0;
            float ys = fminf(fmaxf(cyl + (float)(j - 3), 0.f), (float)(Wl - 1));
            int y0 = min((int)floorf(ys), Wl - 2);
            y0a[j] = y0; wya[j] = ys - (float)y0;
        }
        int xb = x0a[0], yb = y0a[0];

        long fr = LOFF[l] + (long)sfr * Wl * Wl;
        // 64 patch dots: warp w handles positions w*16 .. w*16+15
#pragma unroll 4
        for (int i = 0; i < 16; ++i) {
            int p = warp * 16 + i;
            int iy = p >> 3, ix = p & 7;
            int xx = min(xb + ix, Wl - 1);
            int yy = min(yb + iy, Wl - 1);
            const float4 f = *(const float4*)(pbase + (fr + (long)yy * Wl + xx) * C + lane * 4);
            float d = f.x * t4.x + f.y * t4.y + f.z * t4.z + f.w * t4.w;
            d += __shfl_xor_sync(0xffffffffu, d, 16);
            d += __shfl_xor_sync(0xffffffffu, d, 8);
            d += __shfl_xor_sync(0xffffffffu, d, 4);
            d += __shfl_xor_sync(0xffffffffu, d, 2);
            d += __shfl_xor_sync(0xffffffffu, d, 1);
            if (lane == 0) patch[p] = d * INV_SQRT_C;
        }
        __syncthreads();

        if (tid < KK) {
            int kx = tid % 7, ky = tid / 7;
            int ix = x0a[kx] - xb;
            int iy = y0a[ky] - yb;
            float wx = wxa[kx], wy = wya[ky];
            float v = patch[iy * 8 + ix]           * (1.f - wx) * (1.f - wy)
                    + patch[iy * 8 + ix + 1]       * wx         * (1.f - wy)
                    + patch[(iy + 1) * 8 + ix]     * (1.f - wx) * wy
                    + patch[(iy + 1) * 8 + ix + 1] * wx         * wy;
            outcorr[l * KK + tid] = v;
        }
        __syncthreads();
    }

    // current triplane feature: bilinear at level 0, frame s
    {
        float xs = fminf(fmaxf(cx, 0.f), (float)(W - 1));
        float ys = fminf(fmaxf(cy, 0.f), (float)(H - 1));
        int x0 = min((int)floorf(xs), W - 2);
        int y0 = min((int)floorf(ys), H - 2);
        float wx = xs - (float)x0, wy = ys - (float)y0;
        const float* __restrict__ b = pbase + (((long)sfr * H + y0) * W + x0) * C + tid;
        float v00 = b[0], v01 = b[C];
        float v10 = b[(long)W * C], v11 = b[(long)W * C + C];
        float v = v00 * (1.f - wx) * (1.f - wy) + v01 * wx * (1.f - wy)
                + v10 * (1.f - wx) * wy + v11 * wx * wy;
        out[(long)sn * OUT_F + 3 * LEVELS * KK + plane * C + tid] = v;
    }
}

// ---------------------------------------------------------------------------
extern "C" void kernel_launch(void* const* d_in, const int* in_sizes, int n_in,
                              void* d_out, int out_size) {
    const float* fxy    = (const float*)d_in[0];
    const float* fyz    = (const float*)d_in[1];
    const float* fxz    = (const float*)d_in[2];
    const float* coords = (const float*)d_in[3];
    const int*   qt     = (const int*)d_in[4];
    float* out = (float*)d_out;
    (void)in_sizes; (void)n_in; (void)out_size;

    // 1) fused transpose + L1 pool
    {
        dim3 grid(S * 64, 16, 3), block(32, 8);
        transpose_pool_kernel<<<grid, block>>>(fxy, fyz, fxz);
    }
    // 2) fused L2+L3 pools
    {
        dim3 grid(S * 16, 1, 3);
        pool23_kernel<<<grid, 256>>>();
    }
    // 3) main lookup (tfeat inlined)
    {
        dim3 grid(S * N, 3);
        main_kernel<<<grid, 128>>>(coords, qt, out);
    }
}

// round 7
// speedup vs baseline: 1.7764x; 1.5108x over previous
#include <cuda_runtime.h>
#include <cuda_fp16.h>

#define S 8
#define N 512
#define C 128
#define H 128
#define W 128
#define LEVELS 4
#define KK 49
#define OUT_F 972
#define PLANE_ELEMS 22282240   // (8*(128*128+64*64+32*32+16*16)) * 128

// Scratch: channel-last fp16 fmap pyramid per plane (static device global)
__device__ __half g_pyr[3][PLANE_ELEMS];

// Level offsets in "position" units (positions * C = element offset)
// L0: 0        (S*16384)
// L1: 131072   (S*4096)
// L2: 163840   (S*1024)
// L3: 172032   (S*256)

// ---------------------------------------------------------------------------
// 1) Fused transpose + L1 pool: [S,C,H,W] fp32 -> [S,H,W,C] fp16 L0 + fp16 L1
//    Block covers (s, h-pair) x (32c x 32w tile). grid (S*64, 16, 3)
// ---------------------------------------------------------------------------
__global__ void transpose_pool_kernel(const float* __restrict__ in0,
                                      const float* __restrict__ in1,
                                      const float* __restrict__ in2) {
    int plane = blockIdx.z;
    const float* __restrict__ in = (plane == 0) ? in0 : (plane == 1) ? in1 : in2;
    __half* __restrict__ out = g_pyr[plane];

    int shp = blockIdx.x;            // s*64 + hp
    int s = shp >> 6;
    int hp = shp & 63;               // h-pair: rows 2hp, 2hp+1
    int tileid = blockIdx.y;
    int c0 = (tileid >> 2) * 32;
    int w0 = (tileid & 3) * 32;

    __shared__ float t0[32][33];     // [c_off][w_off] row 2hp
    __shared__ float t1[32][33];     // row 2hp+1
    int tx = threadIdx.x, ty = threadIdx.y;   // (32, 8)

    const float* __restrict__ inp = in + (size_t)s * C * H * W + (size_t)(2 * hp) * W;
#pragma unroll
    for (int i = 0; i < 32; i += 8) {
        t0[ty + i][tx] = inp[(size_t)(c0 + ty + i) * (H * W) + (w0 + tx)];
        t1[ty + i][tx] = inp[(size_t)(c0 + ty + i) * (H * W) + W + (w0 + tx)];
    }
    __syncthreads();

    // L0 writes (channel-last, fp16)
    __half* __restrict__ o0 = out + (size_t)(s * H + 2 * hp) * W * C;
    __half* __restrict__ o1 = o0 + (size_t)W * C;
#pragma unroll
    for (int i = 0; i < 32; i += 8) {
        o0[(size_t)(w0 + ty + i) * C + (c0 + tx)] = __float2half(t0[tx][ty + i]);
        o1[(size_t)(w0 + ty + i) * C + (c0 + tx)] = __float2half(t1[tx][ty + i]);
    }

    // L1 writes: pool 2x2 in fp32, store fp16
    const long L1o = 131072L;
#pragma unroll
    for (int k = 0; k < 2; ++k) {
        int wp = ty + k * 8;                    // 0..15
        float v = t0[tx][2 * wp] + t0[tx][2 * wp + 1]
                + t1[tx][2 * wp] + t1[tx][2 * wp + 1];
        long pos = L1o + (((long)s * 64 + hp) * 64 + (w0 >> 1) + wp);
        out[pos * C + (c0 + tx)] = __float2half(0.25f * v);
    }
}

// ---------------------------------------------------------------------------
// helpers: uint2 = 4 halves
// ---------------------------------------------------------------------------
__device__ __forceinline__ void h4_to_f(uint2 u, float* f) {
    float2 a = __half22float2(*(__half2*)&u.x);
    float2 b = __half22float2(*(__half2*)&u.y);
    f[0] = a.x; f[1] = a.y; f[2] = b.x; f[3] = b.y;
}

// ---------------------------------------------------------------------------
// 2) Fused L1->L2->L3 pool (fp16 in/out, fp32 math). grid (S*16,1,3), 256 thr
// ---------------------------------------------------------------------------
__global__ __launch_bounds__(256) void pool23_kernel() {
    int plane = blockIdx.z;
    int idx = blockIdx.x;              // s*16 + r
    int sfr = idx >> 4;
    int r = idx & 15;
    __half* __restrict__ base = g_pyr[plane];
    const long L1o = 131072L, L2o = 163840L, L3o = 172032L;

    __shared__ float s2[2][32][C];     // L2 values fp32 [row2][col][c] (32 KB)
    int tid = threadIdx.x;
    int warp = tid >> 5, lane = tid & 31;

    // L2: 64 positions (2 rows x 32 cols); warp handles 8; lane = 4 channels
#pragma unroll
    for (int i = 0; i < 8; ++i) {
        int p = warp * 8 + i;
        int row2 = p >> 5, col2 = p & 31;
        int gr2 = r * 2 + row2;
        long l1p = L1o + (((long)sfr * 64 + gr2 * 2) * 64 + col2 * 2);
        float a[4], b[4], c[4], d[4];
        h4_to_f(((const uint2*)(base + l1p * C))[lane], a);
        h4_to_f(((const uint2*)(base + (l1p + 1) * C))[lane], b);
        h4_to_f(((const uint2*)(base + (l1p + 64) * C))[lane], c);
        h4_to_f(((const uint2*)(base + (l1p + 65) * C))[lane], d);
        float v[4];
        __half2 h01, h23;
#pragma unroll
        for (int j = 0; j < 4; ++j) v[j] = 0.25f * (a[j] + b[j] + c[j] + d[j]);
        h01 = __floats2half2_rn(v[0], v[1]);
        h23 = __floats2half2_rn(v[2], v[3]);
        long l2p = L2o + (((long)sfr * 32 + gr2) * 32 + col2);
        uint2 packed = { *(unsigned*)&h01, *(unsigned*)&h23 };
        ((uint2*)(base + l2p * C))[lane] = packed;
#pragma unroll
        for (int j = 0; j < 4; ++j) s2[row2][col2][lane * 4 + j] = v[j];
    }
    __syncthreads();

    // L3: 16 positions in row r; warp handles 2; lane = 4 channels
#pragma unroll
    for (int i = 0; i < 2; ++i) {
        int p = warp * 2 + i;          // col3 0..15
        float v[4];
#pragma unroll
        for (int j = 0; j < 4; ++j) {
            int cc = lane * 4 + j;
            v[j] = 0.25f * (s2[0][2 * p][cc] + s2[0][2 * p + 1][cc]
                          + s2[1][2 * p][cc] + s2[1][2 * p + 1][cc]);
        }
        __half2 h01 = __floats2half2_rn(v[0], v[1]);
        __half2 h23 = __floats2half2_rn(v[2], v[3]);
        long l3p = L3o + (((long)sfr * 16 + r) * 16 + p);
        uint2 packed = { *(unsigned*)&h01, *(unsigned*)&h23 };
        ((uint2*)(base + l3p * C))[lane] = packed;
    }
}

// ---------------------------------------------------------------------------
// 3) Main: per (plane, s, n): inline tfeat + pyramid patch dots + window
//    bilinear + current feature. grid (S*N, 3), 128 threads
// ---------------------------------------------------------------------------
__global__ __launch_bounds__(128) void main_kernel(const float* __restrict__ coords,
                                                   const int* __restrict__ qt,
                                                   float* __restrict__ out) {
    const long LOFF[4] = {0L, 131072L, 163840L, 172032L};
    const float INV_SQRT_C = 0.08838834764831845f;   // 1/sqrt(128)

    int plane = blockIdx.y;
    int sn = blockIdx.x;                  // s*N + n
    int n = sn & (N - 1);
    int sfr = sn >> 9;
    int tid = threadIdx.x;
    int warp = tid >> 5, lane = tid & 31;
    int sub = lane >> 4;                  // which of 2 positions this half-warp reads
    int lh  = lane & 15;                  // lane within half-warp: channels lh*8..+7

    __shared__ float t_sh[C];
    __shared__ float patch[64];

    const __half* __restrict__ pbase = g_pyr[plane];

    float cx, cy;
    {
        const float* __restrict__ cp = coords + (long)sn * 3;
        float x = cp[0], y = cp[1], z = cp[2];
        if (plane == 0)      { cx = x; cy = y; }
        else if (plane == 1) { cx = y; cy = z; }
        else                 { cx = x; cy = z; }
    }

    // --- inline tfeat: bilinear at frame qt[n] with frame-0 coords ---
    {
        const float* __restrict__ cp0 = coords + (long)n * 3;   // s = 0
        float x = cp0[0], y = cp0[1], z = cp0[2];
        float fx, fy;
        if (plane == 0)      { fx = x; fy = y; }
        else if (plane == 1) { fx = y; fy = z; }
        else                 { fx = x; fy = z; }
        fx = fminf(fmaxf(fx, 0.f), (float)(W - 1));
        fy = fminf(fmaxf(fy, 0.f), (float)(H - 1));
        int qx0 = min((int)floorf(fx), W - 2);
        int qy0 = min((int)floorf(fy), H - 2);
        float wx = fx - (float)qx0, wy = fy - (float)qy0;
        int t = qt[n];
        const __half* __restrict__ b = pbase + (((long)t * H + qy0) * W + qx0) * C + tid;
        float v00 = __half2float(b[0]), v01 = __half2float(b[C]);
        float v10 = __half2float(b[(long)W * C]), v11 = __half2float(b[(long)W * C + C]);
        t_sh[tid] = v00 * (1.f - wx) * (1.f - wy) + v01 * wx * (1.f - wy)
                  + v10 * (1.f - wx) * wy + v11 * wx * wy;
    }
    __syncthreads();
    // 8 target channels for this lane's slice
    float4 tA = *(const float4*)&t_sh[lh * 8];
    float4 tB = *(const float4*)&t_sh[lh * 8 + 4];

    float* __restrict__ outcorr = out + (long)sn * OUT_F + plane * (LEVELS * KK);

#pragma unroll
    for (int l = 0; l < LEVELS; ++l) {
        int Wl = W >> l;
        float inv = 1.0f / (float)(1 << l);
        float cxl = cx * inv, cyl = cy * inv;

        int x0a[7]; float wxa[7];
        int y0a[7]; float wya[7];
#pragma unroll
        for (int j = 0; j < 7; ++j) {
            float xs = fminf(fmaxf(cxl + (float)(j - 3), 0.f), (float)(Wl - 1));
            int x0 = min((int)floorf(xs), Wl - 2);
            x0a[j] = x0; wxa[j] = xs - (float)x0;
            float ys = fminf(fmaxf(cyl + (float)(j - 3), 0.f), (float)(Wl - 1));
            int y0 = min((int)floorf(ys), Wl - 2);
            y0a[j] = y0; wya[j] = ys - (float)y0;
        }
        int xb = x0a[0], yb = y0a[0];

        long fr = LOFF[l] + (long)sfr * Wl * Wl;
        // 64 patch dots: warp handles 2 adjacent positions per iter (uint4/lane)
#pragma unroll
        for (int i = 0; i < 8; ++i) {
            int p = warp * 16 + i * 2 + sub;
            int iy = p >> 3, ix = p & 7;
            int xx = min(xb + ix, Wl - 1);
            int yy = min(yb + iy, Wl - 1);
            const uint4 u = *(const uint4*)(pbase + (fr + (long)yy * Wl + xx) * C + lh * 8);
            float2 f0 = __half22float2(*(const __half2*)&u.x);
            float2 f1 = __half22float2(*(const __half2*)&u.y);
            float2 f2 = __half22float2(*(const __half2*)&u.z);
            float2 f3 = __half22float2(*(const __half2*)&u.w);
            float d = f0.x * tA.x + f0.y * tA.y + f1.x * tA.z + f1.y * tA.w
                    + f2.x * tB.x + f2.y * tB.y + f3.x * tB.z + f3.y * tB.w;
            d += __shfl_xor_sync(0xffffffffu, d, 8);
            d += __shfl_xor_sync(0xffffffffu, d, 4);
            d += __shfl_xor_sync(0xffffffffu, d, 2);
            d += __shfl_xor_sync(0xffffffffu, d, 1);
            if (lh == 0) patch[p] = d * INV_SQRT_C;
        }
        __syncthreads();

        if (tid < KK) {
            int kx = tid % 7, ky = tid / 7;
            int ix = x0a[kx] - xb;
            int iy = y0a[ky] - yb;
            float wx = wxa[kx], wy = wya[ky];
            float v = patch[iy * 8 + ix]           * (1.f - wx) * (1.f - wy)
                    + patch[iy * 8 + ix + 1]       * wx         * (1.f - wy)
                    + patch[(iy + 1) * 8 + ix]     * (1.f - wx) * wy
                    + patch[(iy + 1) * 8 + ix + 1] * wx         * wy;
            outcorr[l * KK + tid] = v;
        }
        __syncthreads();
    }

    // current triplane feature: bilinear at level 0, frame s
    {
        float xs = fminf(fmaxf(cx, 0.f), (float)(W - 1));
        float ys = fminf(fmaxf(cy, 0.f), (float)(H - 1));
        int x0 = min((int)floorf(xs), W - 2);
        int y0 = min((int)floorf(ys), H - 2);
        float wx = xs - (float)x0, wy = ys - (float)y0;
        const __half* __restrict__ b = pbase + (((long)sfr * H + y0) * W + x0) * C + tid;
        float v00 = __half2float(b[0]), v01 = __half2float(b[C]);
        float v10 = __half2float(b[(long)W * C]), v11 = __half2float(b[(long)W * C + C]);
        float v = v00 * (1.f - wx) * (1.f - wy) + v01 * wx * (1.f - wy)
                + v10 * (1.f - wx) * wy + v11 * wx * wy;
        out[(long)sn * OUT_F + 3 * LEVELS * KK + plane * C + tid] = v;
    }
}

// ---------------------------------------------------------------------------
extern "C" void kernel_launch(void* const* d_in, const int* in_sizes, int n_in,
                              void* d_out, int out_size) {
    const float* fxy    = (const float*)d_in[0];
    const float* fyz    = (const float*)d_in[1];
    const float* fxz    = (const float*)d_in[2];
    const float* coords = (const float*)d_in[3];
    const int*   qt     = (const int*)d_in[4];
    float* out = (float*)d_out;
    (void)in_sizes; (void)n_in; (void)out_size;

    // 1) fused transpose + L1 pool (fp32 -> fp16)
    {
        dim3 grid(S * 64, 16, 3), block(32, 8);
        transpose_pool_kernel<<<grid, block>>>(fxy, fyz, fxz);
    }
    // 2) fused L2+L3 pools
    {
        dim3 grid(S * 16, 1, 3);
        pool23_kernel<<<grid, 256>>>();
    }
    // 3) main lookup (tfeat inlined)
    {
        dim3 grid(S * N, 3);
        main_kernel<<<grid, 128>>>(coords, qt, out);
    }
}

// round 8
// speedup vs baseline: 2.1956x; 1.2360x over previous
#include <cuda_runtime.h>
#include <cuda_fp16.h>

#define S 8
#define N 512
#define C 128
#define H 128
#define W 128
#define LEVELS 4
#define KK 49
#define OUT_F 972
#define PLANE_ELEMS 22282240   // (8*(128*128+64*64+32*32+16*16)) * 128

// Scratch: channel-last fp16 fmap pyramid per plane (static device global)
__device__ __half g_pyr[3][PLANE_ELEMS];

// Level offsets in "position" units (positions * C = element offset)
// L0: 0        (S*16384)
// L1: 131072   (S*4096)
// L2: 163840   (S*1024)
// L3: 172032   (S*256)

// ---------------------------------------------------------------------------
// 1) Fused transpose + L1 pool: [S,C,H,W] fp32 -> [S,H,W,C] fp16 L0 + fp16 L1
//    Block covers (s, h-pair) x (32c x 32w tile). grid (S*64, 16, 3)
// ---------------------------------------------------------------------------
__global__ void transpose_pool_kernel(const float* __restrict__ in0,
                                      const float* __restrict__ in1,
                                      const float* __restrict__ in2) {
    int plane = blockIdx.z;
    const float* __restrict__ in = (plane == 0) ? in0 : (plane == 1) ? in1 : in2;
    __half* __restrict__ out = g_pyr[plane];

    int shp = blockIdx.x;            // s*64 + hp
    int s = shp >> 6;
    int hp = shp & 63;               // h-pair: rows 2hp, 2hp+1
    int tileid = blockIdx.y;
    int c0 = (tileid >> 2) * 32;
    int w0 = (tileid & 3) * 32;

    __shared__ float t0[32][33];     // [c_off][w_off] row 2hp
    __shared__ float t1[32][33];     // row 2hp+1
    int tx = threadIdx.x, ty = threadIdx.y;   // (32, 8)

    const float* __restrict__ inp = in + (size_t)s * C * H * W + (size_t)(2 * hp) * W;
#pragma unroll
    for (int i = 0; i < 32; i += 8) {
        t0[ty + i][tx] = inp[(size_t)(c0 + ty + i) * (H * W) + (w0 + tx)];
        t1[ty + i][tx] = inp[(size_t)(c0 + ty + i) * (H * W) + W + (w0 + tx)];
    }
    __syncthreads();

    // L0 writes (channel-last, fp16)
    __half* __restrict__ o0 = out + (size_t)(s * H + 2 * hp) * W * C;
    __half* __restrict__ o1 = o0 + (size_t)W * C;
#pragma unroll
    for (int i = 0; i < 32; i += 8) {
        o0[(size_t)(w0 + ty + i) * C + (c0 + tx)] = __float2half(t0[tx][ty + i]);
        o1[(size_t)(w0 + ty + i) * C + (c0 + tx)] = __float2half(t1[tx][ty + i]);
    }

    // L1 writes: pool 2x2 in fp32, store fp16
    const long L1o = 131072L;
#pragma unroll
    for (int k = 0; k < 2; ++k) {
        int wp = ty + k * 8;                    // 0..15
        float v = t0[tx][2 * wp] + t0[tx][2 * wp + 1]
                + t1[tx][2 * wp] + t1[tx][2 * wp + 1];
        long pos = L1o + (((long)s * 64 + hp) * 64 + (w0 >> 1) + wp);
        out[pos * C + (c0 + tx)] = __float2half(0.25f * v);
    }
}

// ---------------------------------------------------------------------------
// helpers: uint2 = 4 halves
// ---------------------------------------------------------------------------
__device__ __forceinline__ void h4_to_f(uint2 u, float* f) {
    float2 a = __half22float2(*(__half2*)&u.x);
    float2 b = __half22float2(*(__half2*)&u.y);
    f[0] = a.x; f[1] = a.y; f[2] = b.x; f[3] = b.y;
}

// ---------------------------------------------------------------------------
// 2) Fused L1->L2->L3 pool (fp16 in/out, fp32 math). grid (S*16,1,3), 256 thr
// ---------------------------------------------------------------------------
__global__ __launch_bounds__(256) void pool23_kernel() {
    int plane = blockIdx.z;
    int idx = blockIdx.x;              // s*16 + r
    int sfr = idx >> 4;
    int r = idx & 15;
    __half* __restrict__ base = g_pyr[plane];
    const long L1o = 131072L, L2o = 163840L, L3o = 172032L;

    __shared__ float s2[2][32][C];     // L2 values fp32 [row2][col][c] (32 KB)
    int tid = threadIdx.x;
    int warp = tid >> 5, lane = tid & 31;

    // L2: 64 positions (2 rows x 32 cols); warp handles 8; lane = 4 channels
#pragma unroll
    for (int i = 0; i < 8; ++i) {
        int p = warp * 8 + i;
        int row2 = p >> 5, col2 = p & 31;
        int gr2 = r * 2 + row2;
        long l1p = L1o + (((long)sfr * 64 + gr2 * 2) * 64 + col2 * 2);
        float a[4], b[4], c[4], d[4];
        h4_to_f(((const uint2*)(base + l1p * C))[lane], a);
        h4_to_f(((const uint2*)(base + (l1p + 1) * C))[lane], b);
        h4_to_f(((const uint2*)(base + (l1p + 64) * C))[lane], c);
        h4_to_f(((const uint2*)(base + (l1p + 65) * C))[lane], d);
        float v[4];
        __half2 h01, h23;
#pragma unroll
        for (int j = 0; j < 4; ++j) v[j] = 0.25f * (a[j] + b[j] + c[j] + d[j]);
        h01 = __floats2half2_rn(v[0], v[1]);
        h23 = __floats2half2_rn(v[2], v[3]);
        long l2p = L2o + (((long)sfr * 32 + gr2) * 32 + col2);
        uint2 packed = { *(unsigned*)&h01, *(unsigned*)&h23 };
        ((uint2*)(base + l2p * C))[lane] = packed;
#pragma unroll
        for (int j = 0; j < 4; ++j) s2[row2][col2][lane * 4 + j] = v[j];
    }
    __syncthreads();

    // L3: 16 positions in row r; warp handles 2; lane = 4 channels
#pragma unroll
    for (int i = 0; i < 2; ++i) {
        int p = warp * 2 + i;          // col3 0..15
        float v[4];
#pragma unroll
        for (int j = 0; j < 4; ++j) {
            int cc = lane * 4 + j;
            v[j] = 0.25f * (s2[0][2 * p][cc] + s2[0][2 * p + 1][cc]
                          + s2[1][2 * p][cc] + s2[1][2 * p + 1][cc]);
        }
        __half2 h01 = __floats2half2_rn(v[0], v[1]);
        __half2 h23 = __floats2half2_rn(v[2], v[3]);
        long l3p = L3o + (((long)sfr * 16 + r) * 16 + p);
        uint2 packed = { *(unsigned*)&h01, *(unsigned*)&h23 };
        ((uint2*)(base + l3p * C))[lane] = packed;
    }
}

// ---------------------------------------------------------------------------
// 3) Main: per (plane, s, n). Warp l owns pyramid level l end-to-end:
//    64 patch dots -> private patch slice -> 49 bilinear taps. No block syncs
//    between levels. grid (S*N, 3), 128 threads.
// ---------------------------------------------------------------------------
__global__ __launch_bounds__(128) void main_kernel(const float* __restrict__ coords,
                                                   const int* __restrict__ qt,
                                                   float* __restrict__ out) {
    const long LOFF[4] = {0L, 131072L, 163840L, 172032L};
    const float INV_SQRT_C = 0.08838834764831845f;   // 1/sqrt(128)

    int plane = blockIdx.y;
    int sn = blockIdx.x;                  // s*N + n
    int n = sn & (N - 1);
    int sfr = sn >> 9;
    int tid = threadIdx.x;
    int warp = tid >> 5, lane = tid & 31;
    int sub = lane >> 4;                  // which of 2 positions this half-warp reads
    int lh  = lane & 15;                  // lane within half-warp: channels lh*8..+7

    __shared__ float t_sh[C];
    __shared__ float patch[4][64];

    const __half* __restrict__ pbase = g_pyr[plane];

    float cx, cy;
    {
        const float* __restrict__ cp = coords + (long)sn * 3;
        float x = cp[0], y = cp[1], z = cp[2];
        if (plane == 0)      { cx = x; cy = y; }
        else if (plane == 1) { cx = y; cy = z; }
        else                 { cx = x; cy = z; }
    }

    // --- inline tfeat: bilinear at frame qt[n] with frame-0 coords ---
    {
        const float* __restrict__ cp0 = coords + (long)n * 3;   // s = 0
        float x = cp0[0], y = cp0[1], z = cp0[2];
        float fx, fy;
        if (plane == 0)      { fx = x; fy = y; }
        else if (plane == 1) { fx = y; fy = z; }
        else                 { fx = x; fy = z; }
        fx = fminf(fmaxf(fx, 0.f), (float)(W - 1));
        fy = fminf(fmaxf(fy, 0.f), (float)(H - 1));
        int qx0 = min((int)floorf(fx), W - 2);
        int qy0 = min((int)floorf(fy), H - 2);
        float wx = fx - (float)qx0, wy = fy - (float)qy0;
        int t = qt[n];
        const __half* __restrict__ b = pbase + (((long)t * H + qy0) * W + qx0) * C + tid;
        float v00 = __half2float(b[0]), v01 = __half2float(b[C]);
        float v10 = __half2float(b[(long)W * C]), v11 = __half2float(b[(long)W * C + C]);
        t_sh[tid] = v00 * (1.f - wx) * (1.f - wy) + v01 * wx * (1.f - wy)
                  + v10 * (1.f - wx) * wy + v11 * wx * wy;
    }
    __syncthreads();
    // 8 target channels for this lane's slice
    float4 tA = *(const float4*)&t_sh[lh * 8];
    float4 tB = *(const float4*)&t_sh[lh * 8 + 4];

    float* __restrict__ outcorr = out + (long)sn * OUT_F + plane * (LEVELS * KK);

    // --- warp 'warp' handles level l = warp ---
    {
        int l = warp;
        int Wl = W >> l;
        float inv = 1.0f / (float)(1 << l);
        float cxl = cx * inv, cyl = cy * inv;

        // patch base corner (tap j=0)
        float xs0 = fminf(fmaxf(cxl - 3.f, 0.f), (float)(Wl - 1));
        int xb = min((int)floorf(xs0), Wl - 2);
        float ys0 = fminf(fmaxf(cyl - 3.f, 0.f), (float)(Wl - 1));
        int yb = min((int)floorf(ys0), Wl - 2);

        long fr = LOFF[l] + (long)sfr * Wl * Wl;

        // 64 patch dots; 2 positions per iter (one per half-warp)
#pragma unroll 8
        for (int i = 0; i < 32; ++i) {
            int p = i * 2 + sub;
            int iy = p >> 3, ix = p & 7;
            int xx = min(xb + ix, Wl - 1);
            int yy = min(yb + iy, Wl - 1);
            const uint4 u = *(const uint4*)(pbase + (fr + (long)yy * Wl + xx) * C + lh * 8);
            float2 f0 = __half22float2(*(const __half2*)&u.x);
            float2 f1 = __half22float2(*(const __half2*)&u.y);
            float2 f2 = __half22float2(*(const __half2*)&u.z);
            float2 f3 = __half22float2(*(const __half2*)&u.w);
            float d = f0.x * tA.x + f0.y * tA.y + f1.x * tA.z + f1.y * tA.w
                    + f2.x * tB.x + f2.y * tB.y + f3.x * tB.z + f3.y * tB.w;
            d += __shfl_xor_sync(0xffffffffu, d, 8);
            d += __shfl_xor_sync(0xffffffffu, d, 4);
            d += __shfl_xor_sync(0xffffffffu, d, 2);
            d += __shfl_xor_sync(0xffffffffu, d, 1);
            if (lh == 0) patch[l][p] = d * INV_SQRT_C;
        }
        __syncwarp();

        // 49 bilinear taps; weights recomputed scalar per tap
        const float* __restrict__ pl = patch[l];
#pragma unroll
        for (int k0 = 0; k0 < 64; k0 += 32) {
            int k = k0 + lane;
            if (k < KK) {
                int ky = k / 7, kx = k - ky * 7;
                float xsk = fminf(fmaxf(cxl + (float)(kx - 3), 0.f), (float)(Wl - 1));
                int xk0 = min((int)floorf(xsk), Wl - 2);
                float wx = xsk - (float)xk0;
                float ysk = fminf(fmaxf(cyl + (float)(ky - 3), 0.f), (float)(Wl - 1));
                int yk0 = min((int)floorf(ysk), Wl - 2);
                float wy = ysk - (float)yk0;
                int ix = xk0 - xb, iy = yk0 - yb;
                float v = pl[iy * 8 + ix]           * (1.f - wx) * (1.f - wy)
                        + pl[iy * 8 + ix + 1]       * wx         * (1.f - wy)
                        + pl[(iy + 1) * 8 + ix]     * (1.f - wx) * wy
                        + pl[(iy + 1) * 8 + ix + 1] * wx         * wy;
                outcorr[l * KK + k] = v;
            }
        }
    }

    // current triplane feature: bilinear at level 0, frame s (independent of patch)
    {
        float xs = fminf(fmaxf(cx, 0.f), (float)(W - 1));
        float ys = fminf(fmaxf(cy, 0.f), (float)(H - 1));
        int x0 = min((int)floorf(xs), W - 2);
        int y0 = min((int)floorf(ys), H - 2);
        float wx = xs - (float)x0, wy = ys - (float)y0;
        const __half* __restrict__ b = pbase + (((long)sfr * H + y0) * W + x0) * C + tid;
        float v00 = __half2float(b[0]), v01 = __half2float(b[C]);
        float v10 = __half2float(b[(long)W * C]), v11 = __half2float(b[(long)W * C + C]);
        float v = v00 * (1.f - wx) * (1.f - wy) + v01 * wx * (1.f - wy)
                + v10 * (1.f - wx) * wy + v11 * wx * wy;
        out[(long)sn * OUT_F + 3 * LEVELS * KK + plane * C + tid] = v;
    }
}

// ---------------------------------------------------------------------------
extern "C" void kernel_launch(void* const* d_in, const int* in_sizes, int n_in,
                              void* d_out, int out_size) {
    const float* fxy    = (const float*)d_in[0];
    const float* fyz    = (const float*)d_in[1];
    const float* fxz    = (const float*)d_in[2];
    const float* coords = (const float*)d_in[3];
    const int*   qt     = (const int*)d_in[4];
    float* out = (float*)d_out;
    (void)in_sizes; (void)n_in; (void)out_size;

    // 1) fused transpose + L1 pool (fp32 -> fp16)
    {
        dim3 grid(S * 64, 16, 3), block(32, 8);
        transpose_pool_kernel<<<grid, block>>>(fxy, fyz, fxz);
    }
    // 2) fused L2+L3 pools
    {
        dim3 grid(S * 16, 1, 3);
        pool23_kernel<<<grid, 256>>>();
    }
    // 3) main lookup (tfeat inlined, warp-per-level)
    {
        dim3 grid(S * N, 3);
        main_kernel<<<grid, 128>>>(coords, qt, out);
    }
}